// round 1
// baseline (speedup 1.0000x reference)
#include <cuda_runtime.h>
#include <cuda_bf16.h>
#include <cstdint>

// Scratch: channel mask as float (1.0 = in top-k, 0.0 = passthrough).
// D is fixed at 4096 for this problem, but guard with MAX_D.
#define MAX_D 8192
__device__ float g_mask[MAX_D];

// ---------------------------------------------------------------------------
// Kernel 1: exact top-k channel mask with lax.top_k tie-breaking.
// rank(d) = #{j : imp[j] > imp[d]} + #{j < d : imp[j] == imp[d]}
// mask[d] = (rank < keep)
// D <= 8192 assumed; importance staged through shared memory.
// ---------------------------------------------------------------------------
__global__ void mask_kernel(const float* __restrict__ imp, int D, int keep) {
    extern __shared__ float s_imp[];
    for (int j = threadIdx.x; j < D; j += blockDim.x) s_imp[j] = imp[j];
    __syncthreads();

    for (int d = blockIdx.x * blockDim.x + threadIdx.x; d < D;
         d += gridDim.x * blockDim.x) {
        float v = s_imp[d];
        int rank = 0;
        #pragma unroll 8
        for (int j = 0; j < D; j++) {
            float u = s_imp[j];
            rank += (u > v) ? 1 : ((u == v && j < d) ? 1 : 0);
        }
        g_mask[d] = (rank < keep) ? 1.0f : 0.0f;
    }
}

// ---------------------------------------------------------------------------
// Kernel 2: streaming elementwise polynomial with per-channel select.
// y = m ? x*(c0 + x*(c1 + x*c2)) : x   ==   y = x + m*(poly - x)
// float4-vectorized; D % 4 == 0 so each float4 covers 4 consecutive channels,
// and the float4 mask index is (i % (D/4)). For D=4096 that's i & 1023 — the
// 16 KB mask vector stays L1-resident.
// ---------------------------------------------------------------------------
__global__ void poly_kernel(const float4* __restrict__ x,
                            const float* __restrict__ coeffs,
                            float4* __restrict__ out,
                            int n4, unsigned int d4_mask) {
    int i = blockIdx.x * blockDim.x + threadIdx.x;
    if (i >= n4) return;

    float c0 = __ldg(&coeffs[0]);
    float c1 = __ldg(&coeffs[1]);
    float c2 = __ldg(&coeffs[2]);

    float4 xv = x[i];
    const float4* m4 = reinterpret_cast<const float4*>(g_mask);
    float4 mv = m4[i & d4_mask];

    float4 r;
    {
        float p = xv.x * fmaf(xv.x, fmaf(xv.x, c2, c1), c0);
        r.x = fmaf(mv.x, p - xv.x, xv.x);
    }
    {
        float p = xv.y * fmaf(xv.y, fmaf(xv.y, c2, c1), c0);
        r.y = fmaf(mv.y, p - xv.y, xv.y);
    }
    {
        float p = xv.z * fmaf(xv.z, fmaf(xv.z, c2, c1), c0);
        r.z = fmaf(mv.z, p - xv.z, xv.z);
    }
    {
        float p = xv.w * fmaf(xv.w, fmaf(xv.w, c2, c1), c0);
        r.w = fmaf(mv.w, p - xv.w, xv.w);
    }
    out[i] = r;
}

extern "C" void kernel_launch(void* const* d_in, const int* in_sizes, int n_in,
                              void* d_out, int out_size) {
    const float* x     = (const float*)d_in[0];   // (B, T, D) fp32
    const float* coef  = (const float*)d_in[1];   // (3,) fp32
    const float* imp   = (const float*)d_in[2];   // (D,) fp32

    int D    = in_sizes[2];                       // 4096
    int keep = (int)(D * 0.5);
    if (keep < 1) keep = 1;
    int n    = in_sizes[0];                       // B*T*D

    // Kernel 1: tiny O(D^2) exact-rank mask.
    {
        int threads = 1024;
        int blocks  = (D + threads - 1) / threads;
        size_t shmem = (size_t)D * sizeof(float);
        mask_kernel<<<blocks, threads, shmem>>>(imp, D, keep);
    }

    // Kernel 2: bandwidth-bound stream.
    {
        int n4 = n / 4;                           // D % 4 == 0, n % 4 == 0
        unsigned int d4_mask = (unsigned int)(D / 4) - 1u;  // D/4 is pow2 (1024)
        int threads = 256;
        int blocks  = (n4 + threads - 1) / threads;
        poly_kernel<<<blocks, threads>>>((const float4*)x, coef,
                                         (float4*)d_out, n4, d4_mask);
    }
}

// round 2
// speedup vs baseline: 2.0515x; 2.0515x over previous
#include <cuda_runtime.h>
#include <cuda_bf16.h>
#include <cstdint>

// Scratch: channel mask as float (1.0 = in top-k, 0.0 = passthrough).
#define MAX_D 8192
__device__ float g_mask[MAX_D];

// ---------------------------------------------------------------------------
// Kernel 1: exact top-k channel mask, lax.top_k tie-breaking, parallelized.
//
// key_j = (monotone(imp_j) << 13) | (8191 - j)  (u64, strictly totally ordered)
// key_j > key_d  <=>  imp_j > imp_d  ||  (imp_j == imp_d && j < d)
// rank(d) = #{j : key_j > key_d};  mask[d] = rank < keep.
//
// Grid: D/128 blocks x 512 threads. Each block:
//   - builds all D keys in shared memory (32 KB for D=4096)
//   - 128 channels x 4 j-slices; each thread scans D/4 keys via ulonglong2
//     (j uniform within a warp -> conflict-free broadcast LDS)
//   - 4-way partial-count reduce in shared, write mask.
// Assumes D % 1024 == 0 (D = 4096 here).
// ---------------------------------------------------------------------------
__device__ __forceinline__ unsigned int monotone_bits(float f) {
    unsigned int b = __float_as_uint(f);
    return (b & 0x80000000u) ? ~b : (b | 0x80000000u);
}

__global__ void mask_kernel(const float* __restrict__ imp, int D, int keep) {
    extern __shared__ unsigned long long s_key[];   // D keys (32 KB @ D=4096)
    __shared__ int s_part[4][128];

    int tid = threadIdx.x;

    for (int j = tid; j < D; j += blockDim.x) {
        unsigned long long m = monotone_bits(imp[j]);
        s_key[j] = (m << 13) | (unsigned int)(8191 - j);
    }
    __syncthreads();

    int chIdx = tid & 127;                 // channel within block
    int sl    = tid >> 7;                  // j-slice 0..3
    int d     = blockIdx.x * 128 + chIdx;
    unsigned long long myk = s_key[d];

    int chunk = D >> 2;                    // D/4 keys per slice
    const ulonglong2* k2 = reinterpret_cast<const ulonglong2*>(s_key);
    int base2 = (sl * chunk) >> 1;         // ulonglong2 index
    int n2    = chunk >> 1;

    int cnt = 0;
    #pragma unroll 4
    for (int j = 0; j < n2; j++) {
        ulonglong2 kk = k2[base2 + j];
        cnt += (kk.x > myk) ? 1 : 0;
        cnt += (kk.y > myk) ? 1 : 0;
    }

    s_part[sl][chIdx] = cnt;
    __syncthreads();

    if (tid < 128) {
        int r = s_part[0][tid] + s_part[1][tid] + s_part[2][tid] + s_part[3][tid];
        g_mask[blockIdx.x * 128 + tid] = (r < keep) ? 1.0f : 0.0f;
    }
}

// ---------------------------------------------------------------------------
// Kernel 2 (unchanged, proven 79.5us @ DRAM=78%): streaming polynomial.
// y = x + m*(poly(x) - x),  poly = x*(c0 + x*(c1 + x*c2))
// ---------------------------------------------------------------------------
__global__ void poly_kernel(const float4* __restrict__ x,
                            const float* __restrict__ coeffs,
                            float4* __restrict__ out,
                            int n4, unsigned int d4_mask) {
    int i = blockIdx.x * blockDim.x + threadIdx.x;
    if (i >= n4) return;

    float c0 = __ldg(&coeffs[0]);
    float c1 = __ldg(&coeffs[1]);
    float c2 = __ldg(&coeffs[2]);

    float4 xv = x[i];
    const float4* m4 = reinterpret_cast<const float4*>(g_mask);
    float4 mv = m4[i & d4_mask];

    float4 r;
    { float p = xv.x * fmaf(xv.x, fmaf(xv.x, c2, c1), c0); r.x = fmaf(mv.x, p - xv.x, xv.x); }
    { float p = xv.y * fmaf(xv.y, fmaf(xv.y, c2, c1), c0); r.y = fmaf(mv.y, p - xv.y, xv.y); }
    { float p = xv.z * fmaf(xv.z, fmaf(xv.z, c2, c1), c0); r.z = fmaf(mv.z, p - xv.z, xv.z); }
    { float p = xv.w * fmaf(xv.w, fmaf(xv.w, c2, c1), c0); r.w = fmaf(mv.w, p - xv.w, xv.w); }
    out[i] = r;
}

extern "C" void kernel_launch(void* const* d_in, const int* in_sizes, int n_in,
                              void* d_out, int out_size) {
    const float* x    = (const float*)d_in[0];   // (B, T, D) fp32
    const float* coef = (const float*)d_in[1];   // (3,) fp32
    const float* imp  = (const float*)d_in[2];   // (D,) fp32

    int D    = in_sizes[2];                      // 4096
    int keep = (int)(D * 0.5);
    if (keep < 1) keep = 1;
    int n    = in_sizes[0];                      // B*T*D

    // Kernel 1: parallel exact-rank mask (D % 1024 == 0 path).
    {
        int blocks  = D / 128;                   // 32
        int threads = 512;
        size_t shmem = (size_t)D * sizeof(unsigned long long);  // 32 KB
        mask_kernel<<<blocks, threads, shmem>>>(imp, D, keep);
    }

    // Kernel 2: bandwidth-bound stream.
    {
        int n4 = n / 4;
        unsigned int d4_mask = (unsigned int)(D / 4) - 1u;      // D/4 pow2
        int threads = 256;
        int blocks  = (n4 + threads - 1) / threads;
        poly_kernel<<<blocks, threads>>>((const float4*)x, coef,
                                         (float4*)d_out, n4, d4_mask);
    }
}

// round 3
// speedup vs baseline: 2.1674x; 1.0565x over previous
#include <cuda_runtime.h>
#include <cuda_bf16.h>
#include <cstdint>

// Scratch: channel mask as float (1.0 = in top-k, 0.0 = passthrough).
#define MAX_D 8192
__device__ float g_mask[MAX_D];

// ---------------------------------------------------------------------------
// Kernel 1: exact top-k channel mask, lax.top_k tie-breaking, chip-wide.
//
// key_j = (monotone(imp_j) << 13) | (8191 - j)  (u64, strict total order)
// key_j > key_d  <=>  imp_j > imp_d  ||  (imp_j == imp_d && j < d)
// rank(d) = #{j : key_j > key_d};  mask[d] = rank < keep.
//
// Grid: D/16 blocks (256 @ D=4096) x 256 threads. Each block:
//   - builds all D keys in shared (32 KB)
//   - 16 channels x 16 j-slices; each thread scans D/16 keys via ulonglong2
//     (addresses warp-uniform per slice -> broadcast LDS, issue-bound)
//   - 16-way partial reduce, write 16 mask entries.
// Assumes D % 256 == 0 (D = 4096 here).
// ---------------------------------------------------------------------------
__device__ __forceinline__ unsigned int monotone_bits(float f) {
    unsigned int b = __float_as_uint(f);
    return (b & 0x80000000u) ? ~b : (b | 0x80000000u);
}

__global__ void mask_kernel(const float* __restrict__ imp, int D, int keep) {
    extern __shared__ unsigned long long s_key[];   // D keys (32 KB @ D=4096)
    __shared__ int s_part[16][17];                  // +1 pad vs bank conflicts

    int tid = threadIdx.x;

    for (int j = tid; j < D; j += blockDim.x) {
        unsigned long long m = monotone_bits(imp[j]);
        s_key[j] = (m << 13) | (unsigned int)(8191 - j);
    }
    __syncthreads();

    int chIdx = tid & 15;                  // channel within block (0..15)
    int sl    = tid >> 4;                  // j-slice (0..15)
    int d     = blockIdx.x * 16 + chIdx;
    unsigned long long myk = s_key[d];

    int chunk = D >> 4;                    // keys per slice (256)
    const ulonglong2* k2 = reinterpret_cast<const ulonglong2*>(s_key);
    int base2 = (sl * chunk) >> 1;
    int n2    = chunk >> 1;                // 128

    int cnt = 0;
    #pragma unroll 8
    for (int j = 0; j < n2; j++) {
        ulonglong2 kk = k2[base2 + j];
        cnt += (kk.x > myk) ? 1 : 0;
        cnt += (kk.y > myk) ? 1 : 0;
    }

    s_part[sl][chIdx] = cnt;
    __syncthreads();

    if (tid < 16) {
        int r = 0;
        #pragma unroll
        for (int s = 0; s < 16; s++) r += s_part[s][tid];
        g_mask[blockIdx.x * 16 + tid] = (r < keep) ? 1.0f : 0.0f;
    }
}

// ---------------------------------------------------------------------------
// Kernel 2 (unchanged, proven ~80us @ DRAM~77%): streaming polynomial.
// y = x + m*(poly(x) - x),  poly = x*(c0 + x*(c1 + x*c2))
// ---------------------------------------------------------------------------
__global__ void poly_kernel(const float4* __restrict__ x,
                            const float* __restrict__ coeffs,
                            float4* __restrict__ out,
                            int n4, unsigned int d4_mask) {
    int i = blockIdx.x * blockDim.x + threadIdx.x;
    if (i >= n4) return;

    float c0 = __ldg(&coeffs[0]);
    float c1 = __ldg(&coeffs[1]);
    float c2 = __ldg(&coeffs[2]);

    float4 xv = x[i];
    const float4* m4 = reinterpret_cast<const float4*>(g_mask);
    float4 mv = m4[i & d4_mask];

    float4 r;
    { float p = xv.x * fmaf(xv.x, fmaf(xv.x, c2, c1), c0); r.x = fmaf(mv.x, p - xv.x, xv.x); }
    { float p = xv.y * fmaf(xv.y, fmaf(xv.y, c2, c1), c0); r.y = fmaf(mv.y, p - xv.y, xv.y); }
    { float p = xv.z * fmaf(xv.z, fmaf(xv.z, c2, c1), c0); r.z = fmaf(mv.z, p - xv.z, xv.z); }
    { float p = xv.w * fmaf(xv.w, fmaf(xv.w, c2, c1), c0); r.w = fmaf(mv.w, p - xv.w, xv.w); }
    out[i] = r;
}

extern "C" void kernel_launch(void* const* d_in, const int* in_sizes, int n_in,
                              void* d_out, int out_size) {
    const float* x    = (const float*)d_in[0];   // (B, T, D) fp32
    const float* coef = (const float*)d_in[1];   // (3,) fp32
    const float* imp  = (const float*)d_in[2];   // (D,) fp32

    int D    = in_sizes[2];                      // 4096
    int keep = (int)(D * 0.5);
    if (keep < 1) keep = 1;
    int n    = in_sizes[0];                      // B*T*D

    // Kernel 1: chip-wide exact-rank mask (D % 256 == 0 path).
    {
        int blocks  = D / 16;                    // 256
        int threads = 256;
        size_t shmem = (size_t)D * sizeof(unsigned long long);  // 32 KB
        mask_kernel<<<blocks, threads, shmem>>>(imp, D, keep);
    }

    // Kernel 2: bandwidth-bound stream (unchanged).
    {
        int n4 = n / 4;
        unsigned int d4_mask = (unsigned int)(D / 4) - 1u;      // D/4 pow2
        int threads = 256;
        int blocks  = (n4 + threads - 1) / threads;
        poly_kernel<<<blocks, threads>>>((const float4*)x, coef,
                                         (float4*)d_out, n4, d4_mask);
    }
}

// round 4
// speedup vs baseline: 2.1883x; 1.0097x over previous
#include <cuda_runtime.h>
#include <cuda_bf16.h>
#include <cstdint>

// Scratch: channel mask as float (1.0 = in top-k, 0.0 = passthrough).
#define MAX_D 8192
__device__ float g_mask[MAX_D];

// ---------------------------------------------------------------------------
// Kernel 1: exact top-k channel mask, lax.top_k tie-breaking, chip-wide.
// key_j = (monotone(imp_j) << 13) | (8191 - j); rank(d) = #{j : key_j > key_d}
// Triggers programmatic launch completion once g_mask is globally visible.
// ---------------------------------------------------------------------------
__device__ __forceinline__ unsigned int monotone_bits(float f) {
    unsigned int b = __float_as_uint(f);
    return (b & 0x80000000u) ? ~b : (b | 0x80000000u);
}

__global__ void mask_kernel(const float* __restrict__ imp, int D, int keep) {
    extern __shared__ unsigned long long s_key[];   // D keys (32 KB @ D=4096)
    __shared__ int s_part[16][17];

    int tid = threadIdx.x;

    for (int j = tid; j < D; j += blockDim.x) {
        unsigned long long m = monotone_bits(imp[j]);
        s_key[j] = (m << 13) | (unsigned int)(8191 - j);
    }
    __syncthreads();

    int chIdx = tid & 15;
    int sl    = tid >> 4;
    int d     = blockIdx.x * 16 + chIdx;
    unsigned long long myk = s_key[d];

    int chunk = D >> 4;
    const ulonglong2* k2 = reinterpret_cast<const ulonglong2*>(s_key);
    int base2 = (sl * chunk) >> 1;
    int n2    = chunk >> 1;

    int cnt = 0;
    #pragma unroll 8
    for (int j = 0; j < n2; j++) {
        ulonglong2 kk = k2[base2 + j];
        cnt += (kk.x > myk) ? 1 : 0;
        cnt += (kk.y > myk) ? 1 : 0;
    }

    s_part[sl][chIdx] = cnt;
    __syncthreads();

    if (tid < 16) {
        int r = 0;
        #pragma unroll
        for (int s = 0; s < 16; s++) r += s_part[s][tid];
        g_mask[blockIdx.x * 16 + tid] = (r < keep) ? 1.0f : 0.0f;
    }

    // Make g_mask visible, then allow the dependent grid to proceed.
    __threadfence();
    __syncthreads();
    cudaTriggerProgrammaticLaunchCompletion();
}

// ---------------------------------------------------------------------------
// Kernel 2: streaming polynomial with PDL overlap.
// Loads x BEFORE the grid-dependency sync so wave-1 DRAM reads overlap the
// mask kernel; reads g_mask only after the sync.
// y = x + m*(poly(x) - x),  poly = x*(c0 + x*(c1 + x*c2))
// ---------------------------------------------------------------------------
__global__ void poly_kernel(const float4* __restrict__ x,
                            const float* __restrict__ coeffs,
                            float4* __restrict__ out,
                            int n4, unsigned int d4_mask) {
    int i = blockIdx.x * blockDim.x + threadIdx.x;
    if (i >= n4) {
        cudaGridDependencySynchronize();
        return;
    }

    // Pre-sync: long-latency global loads that do NOT depend on g_mask.
    float4 xv = x[i];
    float c0 = __ldg(&coeffs[0]);
    float c1 = __ldg(&coeffs[1]);
    float c2 = __ldg(&coeffs[2]);

    float px = xv.x * fmaf(xv.x, fmaf(xv.x, c2, c1), c0);
    float py = xv.y * fmaf(xv.y, fmaf(xv.y, c2, c1), c0);
    float pz = xv.z * fmaf(xv.z, fmaf(xv.z, c2, c1), c0);
    float pw = xv.w * fmaf(xv.w, fmaf(xv.w, c2, c1), c0);

    // Wait for mask_kernel's writes to be visible.
    cudaGridDependencySynchronize();

    const float4* m4 = reinterpret_cast<const float4*>(g_mask);
    float4 mv = m4[i & d4_mask];

    float4 r;
    r.x = fmaf(mv.x, px - xv.x, xv.x);
    r.y = fmaf(mv.y, py - xv.y, xv.y);
    r.z = fmaf(mv.z, pz - xv.z, xv.z);
    r.w = fmaf(mv.w, pw - xv.w, xv.w);
    out[i] = r;
}

extern "C" void kernel_launch(void* const* d_in, const int* in_sizes, int n_in,
                              void* d_out, int out_size) {
    const float* x    = (const float*)d_in[0];   // (B, T, D) fp32
    const float* coef = (const float*)d_in[1];   // (3,) fp32
    const float* imp  = (const float*)d_in[2];   // (D,) fp32

    int D    = in_sizes[2];                      // 4096
    int keep = (int)(D * 0.5);
    if (keep < 1) keep = 1;
    int n    = in_sizes[0];                      // B*T*D

    // Kernel 1: chip-wide exact-rank mask.
    {
        int blocks  = D / 16;                    // 256
        int threads = 256;
        size_t shmem = (size_t)D * sizeof(unsigned long long);  // 32 KB
        mask_kernel<<<blocks, threads, shmem>>>(imp, D, keep);
    }

    // Kernel 2: bandwidth-bound stream, launched with PDL so its prologue
    // overlaps mask_kernel. Falls back to a plain launch if PDL unsupported.
    {
        int n4 = n / 4;
        unsigned int d4_mask = (unsigned int)(D / 4) - 1u;
        int threads = 256;
        int blocks  = (n4 + threads - 1) / threads;

        cudaLaunchAttribute attrs[1];
        attrs[0].id = cudaLaunchAttributeProgrammaticStreamSerialization;
        attrs[0].val.programmaticStreamSerializationAllowed = 1;

        cudaLaunchConfig_t cfg = {};
        cfg.gridDim  = dim3((unsigned)blocks, 1, 1);
        cfg.blockDim = dim3((unsigned)threads, 1, 1);
        cfg.dynamicSmemBytes = 0;
        cfg.stream   = 0;
        cfg.attrs    = attrs;
        cfg.numAttrs = 1;

        cudaError_t err = cudaLaunchKernelEx(&cfg, poly_kernel,
                                             (const float4*)x, coef,
                                             (float4*)d_out, n4, d4_mask);
        if (err != cudaSuccess) {
            // Fallback: plain serialized launch (grid-dep sync degenerates to
            // waiting on an already-complete dependency).
            poly_kernel<<<blocks, threads>>>((const float4*)x, coef,
                                             (float4*)d_out, n4, d4_mask);
        }
    }
}